// round 12
// baseline (speedup 1.0000x reference)
#include <cuda_runtime.h>
#include <cstdint>

// Problem constants
#define NN   8192     // total points
#define NBV  1024     // points per batch
#define BV   8        // batches
#define KV   9        // kernel taps
#define CV   32       // channels
#define CMV  128      // hidden
#define CWROW 288     // K*C floats per point

// ---------------- static scratch (no allocs allowed) ----------------
__device__ __align__(16) float g_cw[NN * CWROW];        // conv_w, [n][k][c]
__device__ __align__(16) float g_part[8 * NN * CV];     // sampled partials (8 nb eighths)
__device__ __align__(16) float g_xl[NN * CV];           // leaky(sampled)
__device__ __align__(16) float g_x[NN * CV];            // bn1(xl)+weights
__device__ __align__(16) float g_hl[NN * CMV];          // leaky(x@W1+b1)
__device__ float g_p1s[64 * CV],  g_p1q[64 * CV];       // bn1 per-block partials
__device__ float g_p2s[256 * CMV], g_p2q[256 * CMV];    // bn2 per-block partials (from k4)

// ---------------- packed f32x2 helpers ----------------
__device__ __forceinline__ unsigned long long pack2(float a, float b) {
    unsigned long long r;
    asm("mov.b64 %0, {%1, %2};" : "=l"(r) : "f"(a), "f"(b));
    return r;
}
__device__ __forceinline__ void unpack2(unsigned long long v, float& a, float& b) {
    asm("mov.b64 {%0, %1}, %2;" : "=f"(a), "=f"(b) : "l"(v));
}
__device__ __forceinline__ void fma2(unsigned long long& d, unsigned long long a,
                                     unsigned long long b) {
    asm("fma.rn.f32x2 %0, %1, %2, %3;" : "=l"(d) : "l"(a), "l"(b), "l"(d));
}
__device__ __forceinline__ unsigned long long mul2(unsigned long long a,
                                                   unsigned long long b) {
    unsigned long long r;
    asm("mul.rn.f32x2 %0, %1, %2;" : "=l"(r) : "l"(a), "l"(b));
    return r;
}

// ---------------- cp.async helpers ----------------
__device__ __forceinline__ uint32_t smem_u32(const void* p) {
    uint32_t a;
    asm("{ .reg .u64 t; cvta.to.shared.u64 t, %1; cvt.u32.u64 %0, t; }" : "=r"(a) : "l"(p));
    return a;
}
__device__ __forceinline__ void cpa16(uint32_t s, const void* g) {
    asm volatile("cp.async.cg.shared.global [%0], [%1], 16;" :: "r"(s), "l"(g));
}
#define CPA_COMMIT() asm volatile("cp.async.commit_group;" ::: "memory")
#define CPA_WAIT(n)  asm volatile("cp.async.wait_group %0;" :: "n"(n) : "memory")

// ---------------- K1: conv_w[n][k][d] = sum_c weights[n][c] * KW[k][c][d] ----------------
__global__ __launch_bounds__(288) void k1_cw(const float* __restrict__ weights,
                                             const float* __restrict__ KW) {
    __shared__ __align__(16) float wS[64 * CV];   // 8KB
    int t = threadIdx.x;
    int k = t / 32, d = t % 32;
    int n0 = blockIdx.x * 64;

    float KWr[CV];
#pragma unroll
    for (int c = 0; c < CV; c++) KWr[c] = KW[k * CV * CV + c * CV + d];

    for (int i = t; i < 64 * CV; i += 288) wS[i] = weights[(size_t)n0 * CV + i];
    __syncthreads();

#pragma unroll 2
    for (int nl = 0; nl < 64; nl++) {
        const float4* wr = reinterpret_cast<const float4*>(&wS[nl * CV]);
        float acc = 0.f;
#pragma unroll
        for (int p = 0; p < 8; p++) {
            float4 v = wr[p];
            acc += KWr[4*p+0] * v.x + KWr[4*p+1] * v.y
                 + KWr[4*p+2] * v.z + KWr[4*p+3] * v.w;
        }
        g_cw[(size_t)(n0 + nl) * CWROW + t] = acc;
    }
}

// ---------------- K2: fused Kmat * conv_w; warp-autonomous cp.async pipeline ----------------
// grid = 8 batches x 8 n-tiles(128) x 8 nb-eighths(128) = 512 CTAs, 128 threads.
// Each WARP stages its own 4-neighbor chunks; no __syncthreads in the mainloop.
#define WNB 4   // neighbors per chunk
__global__ __launch_bounds__(128) void k2_sample(const float* __restrict__ pos,
                                                 const float* __restrict__ kpos) {
    __shared__ __align__(16) float cwS[4][2][WNB * CWROW];   // 4 warps x 2 bufs x 4.6KB
    __shared__ __align__(16) float pW[4][2][8];

    int t    = threadIdx.x;
    int wid  = t >> 5, lane = t & 31;
    int bid  = blockIdx.x;
    int q    = bid & 7;          // nb eighth
    int tile = (bid >> 3) & 7;   // n tile
    int b    = bid >> 6;         // batch

    int n = b * NBV + tile * 128 + t;   // row = t (warp w covers rows 32w..32w+31)
    float px = pos[2 * n], py = pos[2 * n + 1];

    // kernel grid is separable: kpos[k] = (g[k/3], g[k%3])
    float gvx[3], gvy[3];
#pragma unroll
    for (int i = 0; i < 3; i++) { gvx[i] = kpos[2 * (3 * i)]; gvy[i] = kpos[2 * i + 1]; }

    unsigned long long acc2[16];
#pragma unroll
    for (int i = 0; i < 16; i++) acc2[i] = 0ULL;

    int nb0 = b * NBV + q * 128;

    // per-warp stage of chunk ci (4 neighbors) into its own buffer
    auto stage = [&](int ci, int buf) {
        const float4* src = reinterpret_cast<const float4*>(
            &g_cw[(size_t)(nb0 + ci * WNB) * CWROW]);
        uint32_t dst = smem_u32(&cwS[wid][buf][0]);
#pragma unroll
        for (int r = 0; r < 9; r++) {
            int i = lane + 32 * r;               // 288 float4s
            cpa16(dst + 16 * i, src + i);
        }
        if (lane < 2)
            cpa16(smem_u32(&pW[wid][buf][0]) + 16 * lane,
                  reinterpret_cast<const float4*>(&pos[(size_t)2 * (nb0 + ci * WNB)]) + lane);
    };

    stage(0, 0);
    CPA_COMMIT();

#pragma unroll 1
    for (int ci = 0; ci < 32; ci++) {
        int buf = ci & 1;
        if (ci + 1 < 32) { stage(ci + 1, (ci + 1) & 1); CPA_COMMIT(); CPA_WAIT(1); }
        else            { CPA_WAIT(0); }
        __syncwarp();

#pragma unroll
        for (int j = 0; j < WNB; j++) {
            float dX = px - pW[wid][buf][2 * j], dY = py - pW[wid][buf][2 * j + 1];
            float ex[3], ey[3];
#pragma unroll
            for (int g = 0; g < 3; g++) {
                float ax = dX - gvx[g];
                float ay = dY - gvy[g];
                ex[g] = __expf(-2.0f * ax * ax);
                ey[g] = __expf(-2.0f * ay * ay);
            }
            unsigned long long ex2[3], ey2[3];
#pragma unroll
            for (int g = 0; g < 3; g++) {
                ex2[g] = pack2(ex[g], ex[g]);
                ey2[g] = pack2(ey[g], ey[g]);
            }
#pragma unroll
            for (int k = 0; k < KV; k++) {
                unsigned long long w2 = mul2(ex2[k / 3], ey2[k % 3]);
                const ulonglong2* cw2 =
                    reinterpret_cast<const ulonglong2*>(&cwS[wid][buf][j * CWROW + k * CV]);
#pragma unroll
                for (int p = 0; p < 8; p++) {
                    ulonglong2 v = cw2[p];
                    fma2(acc2[2 * p],     v.x, w2);
                    fma2(acc2[2 * p + 1], v.y, w2);
                }
            }
        }
        __syncwarp();   // all lanes done reading buf before next stage overwrites it
    }

    float* outp = &g_part[(size_t)q * NN * CV + (size_t)n * CV];
#pragma unroll
    for (int p = 0; p < 8; p++) {
        float4 v;
        unpack2(acc2[2 * p],     v.x, v.y);
        unpack2(acc2[2 * p + 1], v.z, v.w);
        reinterpret_cast<float4*>(outp)[p] = v;
    }
}

// ---------------- K3: xl = leaky(sum of 8 partials); coalesced per-block stats ----------------
__global__ __launch_bounds__(256) void k3_xl(void) {
    int t = threadIdx.x, blk = blockIdx.x;
    size_t base = (size_t)blk * 128 * CV;
    float s = 0.f, s2 = 0.f;
    for (int idx = t; idx < 128 * CV; idx += 256) {
        size_t off = base + idx;
        float v = 0.f;
#pragma unroll
        for (int sl = 0; sl < 8; sl++) v += g_part[(size_t)sl * NN * CV + off];
        float xl = (v >= 0.f) ? v : 0.01f * v;
        g_xl[off] = xl;
        s += xl; s2 += xl * xl;
    }
    __shared__ float rs[256], rq[256];
    rs[t] = s; rq[t] = s2; __syncthreads();
    if (t < CV) {
        float a = 0.f, bb = 0.f;
#pragma unroll
        for (int j = 0; j < 256; j += 32) { a += rs[t + j]; bb += rq[t + j]; }
        g_p1s[blk * CV + t] = a; g_p1q[blk * CV + t] = bb;
    }
}

// ---------------- K4: x = bn1(xl)+weights; hl = leaky(x@W1+b1); bn2 partials fused ----------------
// grid = 256 blocks x 256 threads; block = 32 n-rows x 8 j-groups(16 each).
__global__ __launch_bounds__(256) void k4_mlp1(const float* __restrict__ weights,
                                               const float* __restrict__ gamma1,
                                               const float* __restrict__ beta1,
                                               const float* __restrict__ W1,
                                               const float* __restrict__ b1) {
    __shared__ __align__(16) float W1s[CV * CMV];
    __shared__ float xS[32 * 33];
    __shared__ float sc1[CV], sh1[CV], b1s[CMV];
    __shared__ float rs[256], rq[256];
    int t = threadIdx.x, blk = blockIdx.x;
    int n0 = blk * 32;

    for (int i = t; i < CV * CMV; i += 256) W1s[i] = W1[i];
    if (t < CMV) b1s[t] = b1[t];
    for (int i = t; i < 32 * CV; i += 256) {
        int nl = i >> 5, c = i & 31;
        xS[nl * 33 + c] = g_xl[(size_t)(n0 + nl) * CV + c];
    }
    {
        int c = t & 31, g = t >> 5;
        float s = 0.f, s2 = 0.f;
        for (int j = g; j < 64; j += 8) { s += g_p1s[j * CV + c]; s2 += g_p1q[j * CV + c]; }
        rs[t] = s; rq[t] = s2;
    }
    __syncthreads();
    if (t < CV) {
        float s = 0.f, s2 = 0.f;
#pragma unroll
        for (int g = 0; g < 8; g++) { s += rs[g * 32 + t]; s2 += rq[g * 32 + t]; }
        float mu  = s * (1.0f / NN);
        float var = s2 * (1.0f / NN) - mu * mu;
        float inv = rsqrtf(var + 1e-5f);
        float sc  = gamma1[t] * inv;
        sc1[t] = sc; sh1[t] = beta1[t] - mu * sc;
    }
    __syncthreads();

    for (int i = t; i < 32 * CV; i += 256) {
        int nl = i >> 5, c = i & 31;
        float xv = fmaf(xS[nl * 33 + c], sc1[c], sh1[c])
                 + weights[(size_t)(n0 + nl) * CV + c];
        xS[nl * 33 + c] = xv;
        g_x[(size_t)(n0 + nl) * CV + c] = xv;
    }
    __syncthreads();

    int nl = t & 31, jq = t >> 5, jb = jq * 16;
    unsigned long long acc2[8];
#pragma unroll
    for (int i = 0; i < 8; i++) acc2[i] = pack2(b1s[jb + 2 * i], b1s[jb + 2 * i + 1]);
#pragma unroll
    for (int c = 0; c < CV; c++) {
        float xc = xS[nl * 33 + c];
        unsigned long long xc2 = pack2(xc, xc);
        const ulonglong2* wr = reinterpret_cast<const ulonglong2*>(&W1s[c * CMV + jb]);
#pragma unroll
        for (int p = 0; p < 4; p++) {
            ulonglong2 v = wr[p];
            fma2(acc2[2 * p],     v.x, xc2);
            fma2(acc2[2 * p + 1], v.y, xc2);
        }
    }
    float* hl = &g_hl[(size_t)(n0 + nl) * CMV + jb];
#pragma unroll
    for (int p = 0; p < 4; p++) {
        float h0, h1, h2, h3;
        unpack2(acc2[2 * p],     h0, h1);
        unpack2(acc2[2 * p + 1], h2, h3);
        float4 v;
        v.x = (h0 >= 0.f) ? h0 : 0.01f * h0;
        v.y = (h1 >= 0.f) ? h1 : 0.01f * h1;
        v.z = (h2 >= 0.f) ? h2 : 0.01f * h2;
        v.w = (h3 >= 0.f) ? h3 : 0.01f * h3;
        reinterpret_cast<float4*>(hl)[p] = v;
    }

    // ---- fused bn2 partial sums over this block's 32x128 hl tile ----
    __syncthreads();   // CTA-scope: make all hl stores visible to the block
    {
        float s = 0.f, s2 = 0.f;
        size_t base = (size_t)n0 * CMV;
        for (int idx = t; idx < 32 * CMV; idx += 256) {   // channel = idx&127 = t&127 const
            float v = g_hl[base + idx];
            s += v; s2 += v * v;
        }
        rs[t] = s; rq[t] = s2;
        __syncthreads();
        if (t < CMV) {
            g_p2s[blk * CMV + t] = rs[t] + rs[t + CMV];
            g_p2q[blk * CMV + t] = rq[t] + rq[t + CMV];
        }
    }
}

// ---------------- K6: h = bn2(hl); mlp_out = h@W2 + b2; outputs via SMEM bounce ----------------
// grid = 128 blocks x 256 threads; block = 64 n-rows x 4 j-groups(9 each).
__global__ __launch_bounds__(256) void k6_final(const float* __restrict__ pos,
                                                const float* __restrict__ gamma2,
                                                const float* __restrict__ beta2,
                                                const float* __restrict__ W2,
                                                const float* __restrict__ b2,
                                                float* __restrict__ out) {
    __shared__ float W2s[CMV * 36];     // 18KB (padded 34->36)
    __shared__ float hlS[64 * 129];     // 33KB normalized h tile, pad 129
    __shared__ float outS[64 * 36];     // 9.2KB output bounce
    __shared__ float sc2[CMV], sh2[CMV], b2s[36];
    __shared__ float rs[256], rq[256];
    int t = threadIdx.x, blk = blockIdx.x;
    int n0 = blk * 64;

    for (int i = t; i < CMV * 36; i += 256) {
        int d = i / 36, j = i % 36;
        W2s[i] = (j < 34) ? W2[d * 34 + j] : 0.f;
    }
    if (t < 36) b2s[t] = (t < 34) ? b2[t] : 0.f;
    {
        int c = t & 127, hf = t >> 7;
        float s = 0.f, s2 = 0.f;
#pragma unroll 8
        for (int j = hf * 128; j < hf * 128 + 128; j++) {
            s += g_p2s[j * CMV + c]; s2 += g_p2q[j * CMV + c];
        }
        rs[t] = s; rq[t] = s2;
    }
    __syncthreads();
    if (t < CMV) {
        float s  = rs[t] + rs[t + 128];
        float s2 = rq[t] + rq[t + 128];
        float mu  = s * (1.0f / NN);
        float var = s2 * (1.0f / NN) - mu * mu;
        float inv = rsqrtf(var + 1e-5f);
        float sc  = gamma2[t] * inv;
        sc2[t] = sc; sh2[t] = beta2[t] - mu * sc;
    }
    __syncthreads();

    for (int i = t; i < 64 * CMV; i += 256) {
        int nl = i >> 7, d = i & 127;
        hlS[nl * 129 + d] = fmaf(g_hl[(size_t)n0 * CMV + i], sc2[d], sh2[d]);
    }
    __syncthreads();

    int nl = t & 63, qq = t >> 6, jb = qq * 9;
    float acc[9];
#pragma unroll
    for (int j = 0; j < 9; j++) acc[j] = b2s[jb + j];
#pragma unroll 4
    for (int d = 0; d < CMV; d++) {
        float hn = hlS[nl * 129 + d];
        const float* wr = &W2s[d * 36 + jb];
#pragma unroll
        for (int j = 0; j < 9; j++) acc[j] += hn * wr[j];
    }
#pragma unroll
    for (int j = 0; j < 9; j++) outS[nl * 36 + jb + j] = acc[j];
    __syncthreads();

    for (int i = t; i < 64 * 34; i += 256) {
        int nl2 = i / 34, jg = i % 34;
        int n = n0 + nl2;
        float v = outS[nl2 * 36 + jg];
        if (jg < 2)
            out[2 * n + jg] = pos[2 * n + jg] + v;
        else
            out[(size_t)NN * 2 + (size_t)n * CV + (jg - 2)]
                = g_x[(size_t)n * CV + (jg - 2)] + v;
    }
}

// ---------------- launch ----------------
extern "C" void kernel_launch(void* const* d_in, const int* in_sizes, int n_in,
                              void* d_out, int out_size) {
    (void)in_sizes; (void)n_in; (void)out_size;
    const float* positions = (const float*)d_in[0];
    const float* weights   = (const float*)d_in[1];
    // d_in[2] = batch (int32, uniform NB) — unused
    const float* kpos      = (const float*)d_in[3];
    const float* KW        = (const float*)d_in[4];
    const float* g1        = (const float*)d_in[5];
    const float* be1       = (const float*)d_in[6];
    const float* W1        = (const float*)d_in[7];
    const float* b1        = (const float*)d_in[8];
    const float* g2        = (const float*)d_in[9];
    const float* be2       = (const float*)d_in[10];
    const float* W2        = (const float*)d_in[11];
    const float* b2        = (const float*)d_in[12];
    float* out = (float*)d_out;

    k1_cw<<<128, 288>>>(weights, KW);
    k2_sample<<<512, 128>>>(positions, kpos);
    k3_xl<<<64, 256>>>();
    k4_mlp1<<<256, 256>>>(weights, g1, be1, W1, b1);
    k6_final<<<128, 256>>>(positions, g2, be2, W2, b2, out);
}

// round 13
// speedup vs baseline: 1.1495x; 1.1495x over previous
#include <cuda_runtime.h>
#include <cstdint>

// Problem constants
#define NN   8192     // total points
#define NBV  1024     // points per batch
#define BV   8        // batches
#define KV   9        // kernel taps
#define CV   32       // channels
#define CMV  128      // hidden
#define CWROW 288     // K*C floats per point

// ---------------- static scratch (no allocs allowed) ----------------
__device__ __align__(16) float g_cw[NN * CWROW];        // conv_w, [n][k][c]
__device__ __align__(16) float g_part[8 * NN * CV];     // sampled partials (8 nb eighths)
__device__ __align__(16) float g_xl[NN * CV];           // leaky(sampled)
__device__ __align__(16) float g_x[NN * CV];            // bn1(xl)+weights
__device__ __align__(16) float g_hl[NN * CMV];          // leaky(x@W1+b1)
__device__ float g_p1s[64 * CV],  g_p1q[64 * CV];       // bn1 per-block partials
__device__ float g_p2s[64 * CMV], g_p2q[64 * CMV];      // bn2 per-block partials

// ---------------- packed f32x2 helpers ----------------
__device__ __forceinline__ unsigned long long pack2(float a, float b) {
    unsigned long long r;
    asm("mov.b64 %0, {%1, %2};" : "=l"(r) : "f"(a), "f"(b));
    return r;
}
__device__ __forceinline__ void unpack2(unsigned long long v, float& a, float& b) {
    asm("mov.b64 {%0, %1}, %2;" : "=f"(a), "=f"(b) : "l"(v));
}
__device__ __forceinline__ void fma2(unsigned long long& d, unsigned long long a,
                                     unsigned long long b) {
    asm("fma.rn.f32x2 %0, %1, %2, %3;" : "=l"(d) : "l"(a), "l"(b), "l"(d));
}
__device__ __forceinline__ unsigned long long mul2(unsigned long long a,
                                                   unsigned long long b) {
    unsigned long long r;
    asm("mul.rn.f32x2 %0, %1, %2;" : "=l"(r) : "l"(a), "l"(b));
    return r;
}

// ---------------- cp.async helpers ----------------
__device__ __forceinline__ uint32_t smem_u32(const void* p) {
    uint32_t a;
    asm("{ .reg .u64 t; cvta.to.shared.u64 t, %1; cvt.u32.u64 %0, t; }" : "=r"(a) : "l"(p));
    return a;
}
__device__ __forceinline__ void cpa16(uint32_t s, const void* g) {
    asm volatile("cp.async.cg.shared.global [%0], [%1], 16;" :: "r"(s), "l"(g));
}
#define CPA_COMMIT() asm volatile("cp.async.commit_group;" ::: "memory")
#define CPA_WAIT(n)  asm volatile("cp.async.wait_group %0;" :: "n"(n) : "memory")

// ---------------- K1: conv_w[n][k][d] = sum_c weights[n][c] * KW[k][c][d] ----------------
__global__ __launch_bounds__(288) void k1_cw(const float* __restrict__ weights,
                                             const float* __restrict__ KW) {
    __shared__ __align__(16) float wS[64 * CV];   // 8KB
    int t = threadIdx.x;
    int k = t / 32, d = t % 32;
    int n0 = blockIdx.x * 64;

    float KWr[CV];
#pragma unroll
    for (int c = 0; c < CV; c++) KWr[c] = KW[k * CV * CV + c * CV + d];

    for (int i = t; i < 64 * CV; i += 288) wS[i] = weights[(size_t)n0 * CV + i];
    __syncthreads();

#pragma unroll 2
    for (int nl = 0; nl < 64; nl++) {
        const float4* wr = reinterpret_cast<const float4*>(&wS[nl * CV]);
        float acc = 0.f;
#pragma unroll
        for (int p = 0; p < 8; p++) {
            float4 v = wr[p];
            acc += KWr[4*p+0] * v.x + KWr[4*p+1] * v.y
                 + KWr[4*p+2] * v.z + KWr[4*p+3] * v.w;
        }
        g_cw[(size_t)(n0 + nl) * CWROW + t] = acc;
    }
}

// ---------------- K2: fused Kmat * conv_w; 2 rows/thread, FFMA2, cp.async DB ----------------
// grid = 8 batches x 4 m-tiles(256 rows) x 8 nb-eighths(128) = 256 CTAs, 128 threads.
// Thread owns rows (t, t+128) -> each staged conv_w value feeds 4 fma2 (LDS no longer binds).
#define NBT 16
__global__ __launch_bounds__(128) void k2_sample(const float* __restrict__ pos,
                                                 const float* __restrict__ kpos) {
    __shared__ __align__(16) float cwS[2][NBT * CWROW];   // 2 x 18KB
    __shared__ __align__(16) float pS[2][NBT * 2];

    int t    = threadIdx.x;
    int bid  = blockIdx.x;
    int q    = bid & 7;          // nb eighth
    int tile = (bid >> 3) & 3;   // m tile (256 rows)
    int b    = bid >> 5;         // batch

    int n0 = b * NBV + tile * 256;
    int na = n0 + t, nbr = n0 + t + 128;
    float pxa = pos[2 * na], pya = pos[2 * na + 1];
    float pxb = pos[2 * nbr], pyb = pos[2 * nbr + 1];

    // kernel grid is separable: kpos[k] = (g[k/3], g[k%3])
    float gvx[3], gvy[3];
#pragma unroll
    for (int i = 0; i < 3; i++) { gvx[i] = kpos[2 * (3 * i)]; gvy[i] = kpos[2 * i + 1]; }

    unsigned long long accA[16], accB[16];
#pragma unroll
    for (int i = 0; i < 16; i++) { accA[i] = 0ULL; accB[i] = 0ULL; }

    int nb0 = b * NBV + q * 128;

    auto stage = [&](int ci, int buf) {
        const float4* src = reinterpret_cast<const float4*>(
            &g_cw[(size_t)(nb0 + ci * NBT) * CWROW]);
        uint32_t dst = smem_u32(&cwS[buf][0]);
#pragma unroll
        for (int r = 0; r < 9; r++) {
            int i = t + 128 * r;          // 1152 float4s
            cpa16(dst + 16 * i, src + i);
        }
        if (t < 8)
            cpa16(smem_u32(&pS[buf][0]) + 16 * t,
                  reinterpret_cast<const float4*>(&pos[(size_t)2 * (nb0 + ci * NBT)]) + t);
    };

    stage(0, 0);
    CPA_COMMIT();

#pragma unroll 1
    for (int ci = 0; ci < 8; ci++) {
        int buf = ci & 1;
        if (ci + 1 < 8) { stage(ci + 1, (ci + 1) & 1); CPA_COMMIT(); CPA_WAIT(1); }
        else           { CPA_WAIT(0); }
        __syncthreads();

#pragma unroll 1
        for (int j = 0; j < NBT; j++) {
            float qx = pS[buf][2 * j], qy = pS[buf][2 * j + 1];
            float dXa = pxa - qx, dYa = pya - qy;
            float dXb = pxb - qx, dYb = pyb - qy;
            unsigned long long exa[3], eya[3], exb[3], eyb[3];
#pragma unroll
            for (int g = 0; g < 3; g++) {
                float ax = dXa - gvx[g], ay = dYa - gvy[g];
                float bx = dXb - gvx[g], by = dYb - gvy[g];
                float ea = __expf(-2.0f * ax * ax), fa = __expf(-2.0f * ay * ay);
                float eb = __expf(-2.0f * bx * bx), fb = __expf(-2.0f * by * by);
                exa[g] = pack2(ea, ea);  eya[g] = pack2(fa, fa);
                exb[g] = pack2(eb, eb);  eyb[g] = pack2(fb, fb);
            }
#pragma unroll
            for (int k = 0; k < KV; k++) {
                unsigned long long wA = mul2(exa[k / 3], eya[k % 3]);
                unsigned long long wB = mul2(exb[k / 3], eyb[k % 3]);
                const ulonglong2* cw2 =
                    reinterpret_cast<const ulonglong2*>(&cwS[buf][j * CWROW + k * CV]);
#pragma unroll
                for (int p = 0; p < 8; p++) {
                    ulonglong2 v = cw2[p];
                    fma2(accA[2 * p],     v.x, wA);
                    fma2(accA[2 * p + 1], v.y, wA);
                    fma2(accB[2 * p],     v.x, wB);
                    fma2(accB[2 * p + 1], v.y, wB);
                }
            }
        }
        __syncthreads();   // all warps done with buf before restage
    }

    float* outA = &g_part[(size_t)q * NN * CV + (size_t)na * CV];
    float* outB = &g_part[(size_t)q * NN * CV + (size_t)nbr * CV];
#pragma unroll
    for (int p = 0; p < 8; p++) {
        float4 v;
        unpack2(accA[2 * p],     v.x, v.y);
        unpack2(accA[2 * p + 1], v.z, v.w);
        reinterpret_cast<float4*>(outA)[p] = v;
        unpack2(accB[2 * p],     v.x, v.y);
        unpack2(accB[2 * p + 1], v.z, v.w);
        reinterpret_cast<float4*>(outB)[p] = v;
    }
}

// ---------------- K3: xl = leaky(sum of 8 partials); coalesced per-block stats ----------------
__global__ __launch_bounds__(256) void k3_xl(void) {
    int t = threadIdx.x, blk = blockIdx.x;
    size_t base = (size_t)blk * 128 * CV;
    float s = 0.f, s2 = 0.f;
    for (int idx = t; idx < 128 * CV; idx += 256) {
        size_t off = base + idx;
        float v = 0.f;
#pragma unroll
        for (int sl = 0; sl < 8; sl++) v += g_part[(size_t)sl * NN * CV + off];
        float xl = (v >= 0.f) ? v : 0.01f * v;
        g_xl[off] = xl;
        s += xl; s2 += xl * xl;
    }
    __shared__ float rs[256], rq[256];
    rs[t] = s; rq[t] = s2; __syncthreads();
    if (t < CV) {
        float a = 0.f, bb = 0.f;
#pragma unroll
        for (int j = 0; j < 256; j += 32) { a += rs[t + j]; bb += rq[t + j]; }
        g_p1s[blk * CV + t] = a; g_p1q[blk * CV + t] = bb;
    }
}

// ---------------- K4: x = bn1(xl)+weights; hl = leaky(x@W1+b1), FFMA2 ----------------
// grid = 256 blocks x 256 threads; block = 32 n-rows x 8 j-groups(16 each).
__global__ __launch_bounds__(256) void k4_mlp1(const float* __restrict__ weights,
                                               const float* __restrict__ gamma1,
                                               const float* __restrict__ beta1,
                                               const float* __restrict__ W1,
                                               const float* __restrict__ b1) {
    __shared__ __align__(16) float W1s[CV * CMV];
    __shared__ float xS[32 * 33];
    __shared__ float sc1[CV], sh1[CV], b1s[CMV];
    __shared__ float rs[256], rq[256];
    int t = threadIdx.x, blk = blockIdx.x;
    int n0 = blk * 32;

    for (int i = t; i < CV * CMV; i += 256) W1s[i] = W1[i];
    if (t < CMV) b1s[t] = b1[t];
    for (int i = t; i < 32 * CV; i += 256) {
        int nl = i >> 5, c = i & 31;
        xS[nl * 33 + c] = g_xl[(size_t)(n0 + nl) * CV + c];
    }
    {
        int c = t & 31, g = t >> 5;
        float s = 0.f, s2 = 0.f;
        for (int j = g; j < 64; j += 8) { s += g_p1s[j * CV + c]; s2 += g_p1q[j * CV + c]; }
        rs[t] = s; rq[t] = s2;
    }
    __syncthreads();
    if (t < CV) {
        float s = 0.f, s2 = 0.f;
#pragma unroll
        for (int g = 0; g < 8; g++) { s += rs[g * 32 + t]; s2 += rq[g * 32 + t]; }
        float mu  = s * (1.0f / NN);
        float var = s2 * (1.0f / NN) - mu * mu;
        float inv = rsqrtf(var + 1e-5f);
        float sc  = gamma1[t] * inv;
        sc1[t] = sc; sh1[t] = beta1[t] - mu * sc;
    }
    __syncthreads();

    for (int i = t; i < 32 * CV; i += 256) {
        int nl = i >> 5, c = i & 31;
        float xv = fmaf(xS[nl * 33 + c], sc1[c], sh1[c])
                 + weights[(size_t)(n0 + nl) * CV + c];
        xS[nl * 33 + c] = xv;
        g_x[(size_t)(n0 + nl) * CV + c] = xv;
    }
    __syncthreads();

    int nl = t & 31, jq = t >> 5, jb = jq * 16;
    unsigned long long acc2[8];
#pragma unroll
    for (int i = 0; i < 8; i++) acc2[i] = pack2(b1s[jb + 2 * i], b1s[jb + 2 * i + 1]);
#pragma unroll
    for (int c = 0; c < CV; c++) {
        float xc = xS[nl * 33 + c];
        unsigned long long xc2 = pack2(xc, xc);
        const ulonglong2* wr = reinterpret_cast<const ulonglong2*>(&W1s[c * CMV + jb]);
#pragma unroll
        for (int p = 0; p < 4; p++) {
            ulonglong2 v = wr[p];
            fma2(acc2[2 * p],     v.x, xc2);
            fma2(acc2[2 * p + 1], v.y, xc2);
        }
    }
    float* hl = &g_hl[(size_t)(n0 + nl) * CMV + jb];
#pragma unroll
    for (int p = 0; p < 4; p++) {
        float h0, h1, h2, h3;
        unpack2(acc2[2 * p],     h0, h1);
        unpack2(acc2[2 * p + 1], h2, h3);
        float4 v;
        v.x = (h0 >= 0.f) ? h0 : 0.01f * h0;
        v.y = (h1 >= 0.f) ? h1 : 0.01f * h1;
        v.z = (h2 >= 0.f) ? h2 : 0.01f * h2;
        v.w = (h3 >= 0.f) ? h3 : 0.01f * h3;
        reinterpret_cast<float4*>(hl)[p] = v;
    }
}

// ---------------- K5: bn2 partial sums, coalesced ----------------
__global__ __launch_bounds__(256) void k5_stats2(void) {
    int t = threadIdx.x, blk = blockIdx.x;
    size_t base = (size_t)blk * 128 * CMV;
    float s = 0.f, s2 = 0.f;
    for (int idx = t; idx < 128 * CMV; idx += 256) {
        float v = g_hl[base + idx];
        s += v; s2 += v * v;
    }
    __shared__ float rs[256], rq[256];
    rs[t] = s; rq[t] = s2; __syncthreads();
    if (t < CMV) {
        g_p2s[blk * CMV + t] = rs[t] + rs[t + CMV];
        g_p2q[blk * CMV + t] = rq[t] + rq[t + CMV];
    }
}

// ---------------- K6: h = bn2(hl); mlp_out = h@W2 + b2; outputs via SMEM bounce ----------------
// grid = 128 blocks x 256 threads; block = 64 n-rows x 4 j-groups(9 each).
__global__ __launch_bounds__(256) void k6_final(const float* __restrict__ pos,
                                                const float* __restrict__ gamma2,
                                                const float* __restrict__ beta2,
                                                const float* __restrict__ W2,
                                                const float* __restrict__ b2,
                                                float* __restrict__ out) {
    __shared__ float W2s[CMV * 36];     // 18KB (padded 34->36)
    __shared__ float hlS[64 * 129];     // 33KB normalized h tile, pad 129
    __shared__ float outS[64 * 36];     // 9.2KB output bounce
    __shared__ float sc2[CMV], sh2[CMV], b2s[36];
    __shared__ float rs[256], rq[256];
    int t = threadIdx.x, blk = blockIdx.x;
    int n0 = blk * 64;

    for (int i = t; i < CMV * 36; i += 256) {
        int d = i / 36, j = i % 36;
        W2s[i] = (j < 34) ? W2[d * 34 + j] : 0.f;
    }
    if (t < 36) b2s[t] = (t < 34) ? b2[t] : 0.f;
    {
        int c = t & 127, hf = t >> 7;
        float s = 0.f, s2 = 0.f;
#pragma unroll 8
        for (int j = hf * 32; j < hf * 32 + 32; j++) {
            s += g_p2s[j * CMV + c]; s2 += g_p2q[j * CMV + c];
        }
        rs[t] = s; rq[t] = s2;
    }
    __syncthreads();
    if (t < CMV) {
        float s  = rs[t] + rs[t + 128];
        float s2 = rq[t] + rq[t + 128];
        float mu  = s * (1.0f / NN);
        float var = s2 * (1.0f / NN) - mu * mu;
        float inv = rsqrtf(var + 1e-5f);
        float sc  = gamma2[t] * inv;
        sc2[t] = sc; sh2[t] = beta2[t] - mu * sc;
    }
    __syncthreads();

    for (int i = t; i < 64 * CMV; i += 256) {
        int nl = i >> 7, d = i & 127;
        hlS[nl * 129 + d] = fmaf(g_hl[(size_t)n0 * CMV + i], sc2[d], sh2[d]);
    }
    __syncthreads();

    int nl = t & 63, qq = t >> 6, jb = qq * 9;
    float acc[9];
#pragma unroll
    for (int j = 0; j < 9; j++) acc[j] = b2s[jb + j];
#pragma unroll 4
    for (int d = 0; d < CMV; d++) {
        float hn = hlS[nl * 129 + d];
        const float* wr = &W2s[d * 36 + jb];
#pragma unroll
        for (int j = 0; j < 9; j++) acc[j] += hn * wr[j];
    }
#pragma unroll
    for (int j = 0; j < 9; j++) outS[nl * 36 + jb + j] = acc[j];
    __syncthreads();

    for (int i = t; i < 64 * 34; i += 256) {
        int nl2 = i / 34, jg = i % 34;
        int n = n0 + nl2;
        float v = outS[nl2 * 36 + jg];
        if (jg < 2)
            out[2 * n + jg] = pos[2 * n + jg] + v;
        else
            out[(size_t)NN * 2 + (size_t)n * CV + (jg - 2)]
                = g_x[(size_t)n * CV + (jg - 2)] + v;
    }
}

// ---------------- launch ----------------
extern "C" void kernel_launch(void* const* d_in, const int* in_sizes, int n_in,
                              void* d_out, int out_size) {
    (void)in_sizes; (void)n_in; (void)out_size;
    const float* positions = (const float*)d_in[0];
    const float* weights   = (const float*)d_in[1];
    // d_in[2] = batch (int32, uniform NB) — unused
    const float* kpos      = (const float*)d_in[3];
    const float* KW        = (const float*)d_in[4];
    const float* g1        = (const float*)d_in[5];
    const float* be1       = (const float*)d_in[6];
    const float* W1        = (const float*)d_in[7];
    const float* b1        = (const float*)d_in[8];
    const float* g2        = (const float*)d_in[9];
    const float* be2       = (const float*)d_in[10];
    const float* W2        = (const float*)d_in[11];
    const float* b2        = (const float*)d_in[12];
    float* out = (float*)d_out;

    k1_cw<<<128, 288>>>(weights, KW);
    k2_sample<<<256, 128>>>(positions, kpos);
    k3_xl<<<64, 256>>>();
    k4_mlp1<<<256, 256>>>(weights, g1, be1, W1, b1);
    k5_stats2<<<64, 256>>>();
    k6_final<<<128, 256>>>(positions, g2, be2, W2, b2, out);
}

// round 16
// speedup vs baseline: 1.2017x; 1.0454x over previous
#include <cuda_runtime.h>
#include <cstdint>

// Problem constants
#define NN   8192     // total points
#define NBV  1024     // points per batch
#define BV   8        // batches
#define KV   9        // kernel taps
#define CV   32       // channels
#define CMV  128      // hidden
#define CWROW 288     // K*C floats per point

// ---------------- static scratch (no allocs allowed) ----------------
__device__ __align__(16) float g_cw[NN * CWROW];        // conv_w, [n][k][c]
__device__ __align__(16) float g_part[16 * NN * CV];    // sampled partials (16 nb splits)
__device__ __align__(16) float g_xl[NN * CV];           // leaky(sampled)
__device__ __align__(16) float g_x[NN * CV];            // bn1(xl)+weights
__device__ __align__(16) float g_hl[NN * CMV];          // leaky(x@W1+b1)
__device__ float g_p1s[64 * CV],  g_p1q[64 * CV];       // bn1 per-block partials
__device__ float g_p2s[64 * CMV], g_p2q[64 * CMV];      // bn2 per-block partials

// ---------------- packed f32x2 helpers ----------------
__device__ __forceinline__ unsigned long long pack2(float a, float b) {
    unsigned long long r;
    asm("mov.b64 %0, {%1, %2};" : "=l"(r) : "f"(a), "f"(b));
    return r;
}
__device__ __forceinline__ void unpack2(unsigned long long v, float& a, float& b) {
    asm("mov.b64 {%0, %1}, %2;" : "=f"(a), "=f"(b) : "l"(v));
}
__device__ __forceinline__ void fma2(unsigned long long& d, unsigned long long a,
                                     unsigned long long b) {
    asm("fma.rn.f32x2 %0, %1, %2, %3;" : "=l"(d) : "l"(a), "l"(b), "l"(d));
}
__device__ __forceinline__ unsigned long long mul2(unsigned long long a,
                                                   unsigned long long b) {
    unsigned long long r;
    asm("mul.rn.f32x2 %0, %1, %2;" : "=l"(r) : "l"(a), "l"(b));
    return r;
}

// ---------------- cp.async helpers ----------------
__device__ __forceinline__ uint32_t smem_u32(const void* p) {
    uint32_t a;
    asm("{ .reg .u64 t; cvta.to.shared.u64 t, %1; cvt.u32.u64 %0, t; }" : "=r"(a) : "l"(p));
    return a;
}
__device__ __forceinline__ void cpa16(uint32_t s, const void* g) {
    asm volatile("cp.async.cg.shared.global [%0], [%1], 16;" :: "r"(s), "l"(g));
}
#define CPA_COMMIT() asm volatile("cp.async.commit_group;" ::: "memory")
#define CPA_WAIT(n)  asm volatile("cp.async.wait_group %0;" :: "n"(n) : "memory")

// ---------------- K1: conv_w[n][k][d] = sum_c weights[n][c] * KW[k][c][d] ----------------
__global__ __launch_bounds__(288) void k1_cw(const float* __restrict__ weights,
                                             const float* __restrict__ KW) {
    __shared__ __align__(16) float wS[64 * CV];   // 8KB
    int t = threadIdx.x;
    int k = t / 32, d = t % 32;
    int n0 = blockIdx.x * 64;

    float KWr[CV];
#pragma unroll
    for (int c = 0; c < CV; c++) KWr[c] = KW[k * CV * CV + c * CV + d];

    for (int i = t; i < 64 * CV; i += 288) wS[i] = weights[(size_t)n0 * CV + i];
    __syncthreads();

#pragma unroll 2
    for (int nl = 0; nl < 64; nl++) {
        const float4* wr = reinterpret_cast<const float4*>(&wS[nl * CV]);
        float acc = 0.f;
#pragma unroll
        for (int p = 0; p < 8; p++) {
            float4 v = wr[p];
            acc += KWr[4*p+0] * v.x + KWr[4*p+1] * v.y
                 + KWr[4*p+2] * v.z + KWr[4*p+3] * v.w;
        }
        g_cw[(size_t)(n0 + nl) * CWROW + t] = acc;
    }
}

// ---------------- K2: fused Kmat * conv_w; 4 rows/thread, FFMA2, cp.async DB ----------------
// grid = 8 batches x 2 m-tiles(512 rows) x 16 nb-splits(64) = 256 CTAs, 128 threads.
// Thread owns rows (t, t+128, t+256, t+384): each staged value feeds 8 fma2.
#define NBT 16
__global__ __launch_bounds__(128) void k2_sample(const float* __restrict__ pos,
                                                 const float* __restrict__ kpos) {
    __shared__ __align__(16) float cwS[2][NBT * CWROW];   // 2 x 18KB
    __shared__ __align__(16) float pS[2][NBT * 2];

    int t    = threadIdx.x;
    int bid  = blockIdx.x;
    int q    = bid & 15;         // nb split (64 neighbors)
    int tile = (bid >> 4) & 1;   // m tile (512 rows)
    int b    = bid >> 5;         // batch

    int n0 = b * NBV + tile * 512;
    float pxr[4], pyr[4];
#pragma unroll
    for (int r = 0; r < 4; r++) {
        int n = n0 + t + r * 128;
        pxr[r] = pos[2 * n]; pyr[r] = pos[2 * n + 1];
    }

    // kernel grid is separable: kpos[k] = (g[k/3], g[k%3])
    float gvx[3], gvy[3];
#pragma unroll
    for (int i = 0; i < 3; i++) { gvx[i] = kpos[2 * (3 * i)]; gvy[i] = kpos[2 * i + 1]; }

    unsigned long long acc2[4][16];
#pragma unroll
    for (int r = 0; r < 4; r++)
#pragma unroll
        for (int i = 0; i < 16; i++) acc2[r][i] = 0ULL;

    int nb0 = b * NBV + q * 64;

    auto stage = [&](int ci, int buf) {
        const float4* src = reinterpret_cast<const float4*>(
            &g_cw[(size_t)(nb0 + ci * NBT) * CWROW]);
        uint32_t dst = smem_u32(&cwS[buf][0]);
#pragma unroll
        for (int r = 0; r < 9; r++) {
            int i = t + 128 * r;          // 1152 float4s
            cpa16(dst + 16 * i, src + i);
        }
        if (t < 8)
            cpa16(smem_u32(&pS[buf][0]) + 16 * t,
                  reinterpret_cast<const float4*>(&pos[(size_t)2 * (nb0 + ci * NBT)]) + t);
    };

    stage(0, 0);
    CPA_COMMIT();

#pragma unroll 1
    for (int ci = 0; ci < 4; ci++) {
        int buf = ci & 1;
        if (ci + 1 < 4) { stage(ci + 1, (ci + 1) & 1); CPA_COMMIT(); CPA_WAIT(1); }
        else           { CPA_WAIT(0); }
        __syncthreads();

#pragma unroll 1
        for (int j = 0; j < NBT; j++) {
            float qx = pS[buf][2 * j], qy = pS[buf][2 * j + 1];
            unsigned long long ex2[4][3], ey2[4][3];
#pragma unroll
            for (int r = 0; r < 4; r++) {
                float dX = pxr[r] - qx, dY = pyr[r] - qy;
#pragma unroll
                for (int g = 0; g < 3; g++) {
                    float ax = dX - gvx[g], ay = dY - gvy[g];
                    float ev = __expf(-2.0f * ax * ax);
                    float fv = __expf(-2.0f * ay * ay);
                    ex2[r][g] = pack2(ev, ev);
                    ey2[r][g] = pack2(fv, fv);
                }
            }
#pragma unroll
            for (int k = 0; k < KV; k++) {
                unsigned long long w[4];
#pragma unroll
                for (int r = 0; r < 4; r++) w[r] = mul2(ex2[r][k / 3], ey2[r][k % 3]);
                const ulonglong2* cw2 =
                    reinterpret_cast<const ulonglong2*>(&cwS[buf][j * CWROW + k * CV]);
#pragma unroll
                for (int p = 0; p < 8; p++) {
                    ulonglong2 v = cw2[p];
#pragma unroll
                    for (int r = 0; r < 4; r++) {
                        fma2(acc2[r][2 * p],     v.x, w[r]);
                        fma2(acc2[r][2 * p + 1], v.y, w[r]);
                    }
                }
            }
        }
        __syncthreads();   // all warps done with buf before restage
    }

#pragma unroll
    for (int r = 0; r < 4; r++) {
        int n = n0 + t + r * 128;
        float* outp = &g_part[(size_t)q * NN * CV + (size_t)n * CV];
#pragma unroll
        for (int p = 0; p < 8; p++) {
            float4 v;
            unpack2(acc2[r][2 * p],     v.x, v.y);
            unpack2(acc2[r][2 * p + 1], v.z, v.w);
            reinterpret_cast<float4*>(outp)[p] = v;
        }
    }
}

// ---------------- K3: xl = leaky(sum of 16 partials); coalesced per-block stats ----------------
__global__ __launch_bounds__(256) void k3_xl(void) {
    int t = threadIdx.x, blk = blockIdx.x;
    size_t base = (size_t)blk * 128 * CV;
    float s = 0.f, s2 = 0.f;
    for (int idx = t; idx < 128 * CV; idx += 256) {
        size_t off = base + idx;
        float v = 0.f;
#pragma unroll
        for (int sl = 0; sl < 16; sl++) v += g_part[(size_t)sl * NN * CV + off];
        float xl = (v >= 0.f) ? v : 0.01f * v;
        g_xl[off] = xl;
        s += xl; s2 += xl * xl;
    }
    __shared__ float rs[256], rq[256];
    rs[t] = s; rq[t] = s2; __syncthreads();
    if (t < CV) {
        float a = 0.f, bb = 0.f;
#pragma unroll
        for (int j = 0; j < 256; j += 32) { a += rs[t + j]; bb += rq[t + j]; }
        g_p1s[blk * CV + t] = a; g_p1q[blk * CV + t] = bb;
    }
}

// ---------------- K4: x = bn1(xl)+weights; hl = leaky(x@W1+b1), FFMA2 ----------------
// grid = 64 blocks x 512 threads; block = 128 n-rows x 4 j-groups(32 each).
__global__ __launch_bounds__(512) void k4_mlp1(const float* __restrict__ weights,
                                               const float* __restrict__ gamma1,
                                               const float* __restrict__ beta1,
                                               const float* __restrict__ W1,
                                               const float* __restrict__ b1) {
    __shared__ __align__(16) float W1s[CV * CMV];   // 16KB
    __shared__ float xS[128 * 33];                  // 16.9KB
    __shared__ float sc1[CV], sh1[CV], b1s[CMV];
    __shared__ float rs[512], rq[512];
    int t = threadIdx.x, blk = blockIdx.x;
    int n0 = blk * 128;

    for (int i = t; i < CV * CMV; i += 512) W1s[i] = W1[i];
    if (t < CMV) b1s[t] = b1[t];
    for (int i = t; i < 128 * CV; i += 512) {
        int nl = i >> 5, c = i & 31;
        xS[nl * 33 + c] = g_xl[(size_t)(n0 + nl) * CV + c];
    }
    {
        int c = t & 31, g = t >> 5;   // 16 groups
        float s = 0.f, s2 = 0.f;
        for (int j = g; j < 64; j += 16) { s += g_p1s[j * CV + c]; s2 += g_p1q[j * CV + c]; }
        rs[t] = s; rq[t] = s2;
    }
    __syncthreads();
    if (t < CV) {
        float s = 0.f, s2 = 0.f;
#pragma unroll
        for (int g = 0; g < 16; g++) { s += rs[g * 32 + t]; s2 += rq[g * 32 + t]; }
        float mu  = s * (1.0f / NN);
        float var = s2 * (1.0f / NN) - mu * mu;
        float inv = rsqrtf(var + 1e-5f);
        float sc  = gamma1[t] * inv;
        sc1[t] = sc; sh1[t] = beta1[t] - mu * sc;
    }
    __syncthreads();

    for (int i = t; i < 128 * CV; i += 512) {
        int nl = i >> 5, c = i & 31;
        float xv = fmaf(xS[nl * 33 + c], sc1[c], sh1[c])
                 + weights[(size_t)(n0 + nl) * CV + c];
        xS[nl * 33 + c] = xv;
        g_x[(size_t)(n0 + nl) * CV + c] = xv;
    }
    __syncthreads();

    int nl = t & 127, jq = t >> 7, jb = jq * 32;
    unsigned long long acc2[16];
#pragma unroll
    for (int i = 0; i < 16; i++) acc2[i] = pack2(b1s[jb + 2 * i], b1s[jb + 2 * i + 1]);
#pragma unroll
    for (int c = 0; c < CV; c++) {
        float xc = xS[nl * 33 + c];
        unsigned long long xc2 = pack2(xc, xc);
        const ulonglong2* wr = reinterpret_cast<const ulonglong2*>(&W1s[c * CMV + jb]);
#pragma unroll
        for (int p = 0; p < 8; p++) {
            ulonglong2 v = wr[p];
            fma2(acc2[2 * p],     v.x, xc2);
            fma2(acc2[2 * p + 1], v.y, xc2);
        }
    }
    float* hl = &g_hl[(size_t)(n0 + nl) * CMV + jb];
#pragma unroll
    for (int p = 0; p < 8; p++) {
        float h0, h1, h2, h3;
        unpack2(acc2[2 * p],     h0, h1);
        unpack2(acc2[2 * p + 1], h2, h3);
        float4 v;
        v.x = (h0 >= 0.f) ? h0 : 0.01f * h0;
        v.y = (h1 >= 0.f) ? h1 : 0.01f * h1;
        v.z = (h2 >= 0.f) ? h2 : 0.01f * h2;
        v.w = (h3 >= 0.f) ? h3 : 0.01f * h3;
        reinterpret_cast<float4*>(hl)[p] = v;
    }
}

// ---------------- K5: bn2 partial sums, coalesced ----------------
__global__ __launch_bounds__(256) void k5_stats2(void) {
    int t = threadIdx.x, blk = blockIdx.x;
    size_t base = (size_t)blk * 128 * CMV;
    float s = 0.f, s2 = 0.f;
    for (int idx = t; idx < 128 * CMV; idx += 256) {
        float v = g_hl[base + idx];
        s += v; s2 += v * v;
    }
    __shared__ float rs[256], rq[256];
    rs[t] = s; rq[t] = s2; __syncthreads();
    if (t < CMV) {
        g_p2s[blk * CMV + t] = rs[t] + rs[t + CMV];
        g_p2q[blk * CMV + t] = rq[t] + rq[t + CMV];
    }
}

// ---------------- K6: h = bn2(hl); mlp_out = h@W2 + b2; outputs via SMEM bounce ----------------
// grid = 128 blocks x 256 threads; block = 64 n-rows x 4 j-groups(9 each).
__global__ __launch_bounds__(256) void k6_final(const float* __restrict__ pos,
                                                const float* __restrict__ gamma2,
                                                const float* __restrict__ beta2,
                                                const float* __restrict__ W2,
                                                const float* __restrict__ b2,
                                                float* __restrict__ out) {
    __shared__ float W2s[CMV * 36];     // 18KB (padded 34->36)
    __shared__ float hlS[64 * 129];     // 33KB normalized h tile, pad 129
    __shared__ float outS[64 * 36];     // 9.2KB output bounce
    __shared__ float sc2[CMV], sh2[CMV], b2s[36];
    __shared__ float rs[256], rq[256];
    int t = threadIdx.x, blk = blockIdx.x;
    int n0 = blk * 64;

    for (int i = t; i < CMV * 36; i += 256) {
        int d = i / 36, j = i % 36;
        W2s[i] = (j < 34) ? W2[d * 34 + j] : 0.f;
    }
    if (t < 36) b2s[t] = (t < 34) ? b2[t] : 0.f;
    {
        int c = t & 127, hf = t >> 7;
        float s = 0.f, s2 = 0.f;
#pragma unroll 8
        for (int j = hf * 32; j < hf * 32 + 32; j++) {
            s += g_p2s[j * CMV + c]; s2 += g_p2q[j * CMV + c];
        }
        rs[t] = s; rq[t] = s2;
    }
    __syncthreads();
    if (t < CMV) {
        float s  = rs[t] + rs[t + 128];
        float s2 = rq[t] + rq[t + 128];
        float mu  = s * (1.0f / NN);
        float var = s2 * (1.0f / NN) - mu * mu;
        float inv = rsqrtf(var + 1e-5f);
        float sc  = gamma2[t] * inv;
        sc2[t] = sc; sh2[t] = beta2[t] - mu * sc;
    }
    __syncthreads();

    for (int i = t; i < 64 * CMV; i += 256) {
        int nl = i >> 7, d = i & 127;
        hlS[nl * 129 + d] = fmaf(g_hl[(size_t)n0 * CMV + i], sc2[d], sh2[d]);
    }
    __syncthreads();

    int nl = t & 63, qq = t >> 6, jb = qq * 9;
    float acc[9];
#pragma unroll
    for (int j = 0; j < 9; j++) acc[j] = b2s[jb + j];
#pragma unroll 4
    for (int d = 0; d < CMV; d++) {
        float hn = hlS[nl * 129 + d];
        const float* wr = &W2s[d * 36 + jb];
#pragma unroll
        for (int j = 0; j < 9; j++) acc[j] += hn * wr[j];
    }
#pragma unroll
    for (int j = 0; j < 9; j++) outS[nl * 36 + jb + j] = acc[j];
    __syncthreads();

    for (int i = t; i < 64 * 34; i += 256) {
        int nl2 = i / 34, jg = i % 34;
        int n = n0 + nl2;
        float v = outS[nl2 * 36 + jg];
        if (jg < 2)
            out[2 * n + jg] = pos[2 * n + jg] + v;
        else
            out[(size_t)NN * 2 + (size_t)n * CV + (jg - 2)]
                = g_x[(size_t)n * CV + (jg - 2)] + v;
    }
}

// ---------------- launch ----------------
extern "C" void kernel_launch(void* const* d_in, const int* in_sizes, int n_in,
                              void* d_out, int out_size) {
    (void)in_sizes; (void)n_in; (void)out_size;
    const float* positions = (const float*)d_in[0];
    const float* weights   = (const float*)d_in[1];
    // d_in[2] = batch (int32, uniform NB) — unused
    const float* kpos      = (const float*)d_in[3];
    const float* KW        = (const float*)d_in[4];
    const float* g1        = (const float*)d_in[5];
    const float* be1       = (const float*)d_in[6];
    const float* W1        = (const float*)d_in[7];
    const float* b1        = (const float*)d_in[8];
    const float* g2        = (const float*)d_in[9];
    const float* be2       = (const float*)d_in[10];
    const float* W2        = (const float*)d_in[11];
    const float* b2        = (const float*)d_in[12];
    float* out = (float*)d_out;

    k1_cw<<<128, 288>>>(weights, KW);
    k2_sample<<<256, 128>>>(positions, kpos);
    k3_xl<<<64, 256>>>();
    k4_mlp1<<<64, 512>>>(weights, g1, be1, W1, b1);
    k5_stats2<<<64, 256>>>();
    k6_final<<<128, 256>>>(positions, g2, be2, W2, b2, out);
}